// round 1
// baseline (speedup 1.0000x reference)
#include <cuda_runtime.h>

#define D_MODEL 1024
#define N_TOK   2048
#define N_HEADS 16
#define HEAD_D  64
#define SEQ     512
#define NB      4
#define FFN_D   4096
#define NEXP    8
#define CAPV    512

// ---------------- device scratch (no allocations allowed) ----------------
__device__ float g_h1  [N_TOK * D_MODEL];
__device__ float g_q   [N_TOK * D_MODEL];
__device__ float g_k   [N_TOK * D_MODEL];
__device__ float g_v   [N_TOK * D_MODEL];
__device__ float g_attn[N_TOK * D_MODEL];
__device__ float g_h2  [N_TOK * D_MODEL];
__device__ float g_sc  [(size_t)NB * N_HEADS * SEQ * SEQ];   // 64 MB
__device__ float g_hmid[(size_t)NEXP * CAPV * FFN_D];        // 64 MB
__device__ float g_y   [(size_t)NEXP * CAPV * D_MODEL];      // 16 MB
__device__ int   g_top1[N_TOK];
__device__ int   g_top2[N_TOK];
__device__ float g_p1  [N_TOK];
__device__ float g_p2  [N_TOK];
__device__ int   g_s1  [N_TOK];
__device__ int   g_s2  [N_TOK];
__device__ float g_g1  [N_TOK];
__device__ float g_g2  [N_TOK];
__device__ int   g_disp[NEXP * CAPV];

// ---------------- LayerNorm (one block per token, 256 threads) ----------------
__global__ void ln_kernel(const float* __restrict__ x, const float* __restrict__ gam,
                          const float* __restrict__ bet, float* __restrict__ out) {
    __shared__ float redA[8], redB[8];
    int t = blockIdx.x;
    const float* xr = x + (size_t)t * D_MODEL;
    float v[4]; float s = 0.f;
#pragma unroll
    for (int i = 0; i < 4; i++) { v[i] = xr[threadIdx.x + 256 * i]; s += v[i]; }
#pragma unroll
    for (int o = 16; o; o >>= 1) s += __shfl_xor_sync(~0u, s, o);
    if ((threadIdx.x & 31) == 0) redA[threadIdx.x >> 5] = s;
    __syncthreads();
    if (threadIdx.x == 0) { float r = 0.f; for (int i = 0; i < 8; i++) r += redA[i]; redA[0] = r; }
    __syncthreads();
    float mu = redA[0] * (1.f / D_MODEL);
    float s2 = 0.f;
#pragma unroll
    for (int i = 0; i < 4; i++) { float d = v[i] - mu; s2 += d * d; }
#pragma unroll
    for (int o = 16; o; o >>= 1) s2 += __shfl_xor_sync(~0u, s2, o);
    if ((threadIdx.x & 31) == 0) redB[threadIdx.x >> 5] = s2;
    __syncthreads();
    if (threadIdx.x == 0) { float r = 0.f; for (int i = 0; i < 8; i++) r += redB[i]; redB[0] = r; }
    __syncthreads();
    float rstd = rsqrtf(redB[0] * (1.f / D_MODEL) + 1e-5f);
    float* orow = out + (size_t)t * D_MODEL;
#pragma unroll
    for (int i = 0; i < 4; i++) {
        int c = threadIdx.x + 256 * i;
        orow[c] = (v[i] - mu) * rstd * gam[c] + bet[c];
    }
}

// ---------------- 128x128x16 SGEMM, 256 threads, 8x8 microtile ----------------
// out[z][m][n] = epilogue( sum_k A[z][row(m)][k] * W[z][k][n] )
// epilogue: r = (acc + bias[n]) * scale; r += resid[m][n]; if RELU r = max(r,0)
template <bool RELU, bool GATHER>
__global__ __launch_bounds__(256)
void gemm128(const float* __restrict__ A, const float* __restrict__ W,
             const float* __restrict__ bias, const float* __restrict__ resid,
             float* __restrict__ out, int K, int N, float scale,
             const int* __restrict__ gather,
             long aStride, long wStride, long bStride, long oStride) {
    int z = blockIdx.z;
    const float* Ab = A + (long)z * aStride;
    const float* Wb = W + (long)z * wStride;
    const float* Bb = bias + (long)z * bStride;
    float* Ob = out + (long)z * oStride;

    int m0 = blockIdx.y * 128;
    int n0 = blockIdx.x * 128;

    __shared__ float As[16][132];
    __shared__ float Ws[16][128];

    int tid = threadIdx.x;
    int tx = tid & 15;         // n micro
    int ty = tid >> 4;         // m micro

    // A-tile load mapping: 128 rows x 16 k -> 512 float4, 2 per thread
    int lr0 = tid >> 2;            // 0..63
    int lk  = (tid & 3) * 4;       // 0,4,8,12
    int ar0 = m0 + lr0;
    int ar1 = m0 + lr0 + 64;
    long arow0, arow1;
    if (GATHER) {
        const int* Gb = gather + z * CAPV;
        arow0 = (long)Gb[ar0] * K;
        arow1 = (long)Gb[ar1] * K;
    } else {
        arow0 = (long)ar0 * K;
        arow1 = (long)ar1 * K;
    }
    // W-tile load mapping: 16 k x 32 float4 -> 512 float4, 2 per thread
    int wk = tid >> 5;             // 0..7 (and wk+8)
    int wn = (tid & 31) * 4;

    float c[8][8];
#pragma unroll
    for (int i = 0; i < 8; i++)
#pragma unroll
        for (int j = 0; j < 8; j++) c[i][j] = 0.f;

    for (int k0 = 0; k0 < K; k0 += 16) {
        float4 a0 = *(const float4*)(Ab + arow0 + k0 + lk);
        float4 a1 = *(const float4*)(Ab + arow1 + k0 + lk);
        float4 w0 = *(const float4*)(Wb + (long)(k0 + wk) * N + n0 + wn);
        float4 w1 = *(const float4*)(Wb + (long)(k0 + wk + 8) * N + n0 + wn);
        __syncthreads();
        As[lk + 0][lr0] = a0.x; As[lk + 1][lr0] = a0.y;
        As[lk + 2][lr0] = a0.z; As[lk + 3][lr0] = a0.w;
        As[lk + 0][lr0 + 64] = a1.x; As[lk + 1][lr0 + 64] = a1.y;
        As[lk + 2][lr0 + 64] = a1.z; As[lk + 3][lr0 + 64] = a1.w;
        *(float4*)&Ws[wk][wn]     = w0;
        *(float4*)&Ws[wk + 8][wn] = w1;
        __syncthreads();
#pragma unroll
        for (int kk = 0; kk < 16; kk++) {
            float a[8], b[8];
            *(float4*)&a[0] = *(const float4*)&As[kk][ty * 8];
            *(float4*)&a[4] = *(const float4*)&As[kk][ty * 8 + 4];
            *(float4*)&b[0] = *(const float4*)&Ws[kk][tx * 8];
            *(float4*)&b[4] = *(const float4*)&Ws[kk][tx * 8 + 4];
#pragma unroll
            for (int i = 0; i < 8; i++)
#pragma unroll
                for (int j = 0; j < 8; j++)
                    c[i][j] = fmaf(a[i], b[j], c[i][j]);
        }
    }

#pragma unroll
    for (int i = 0; i < 8; i++) {
        long ro = (long)(m0 + ty * 8 + i) * N;
#pragma unroll
        for (int j0 = 0; j0 < 8; j0 += 4) {
            int n = n0 + tx * 8 + j0;
            float4 bv = *(const float4*)(Bb + n);
            float4 r;
            r.x = (c[i][j0 + 0] + bv.x) * scale;
            r.y = (c[i][j0 + 1] + bv.y) * scale;
            r.z = (c[i][j0 + 2] + bv.z) * scale;
            r.w = (c[i][j0 + 3] + bv.w) * scale;
            if (resid) {
                float4 rv = *(const float4*)(resid + ro + n);
                r.x += rv.x; r.y += rv.y; r.z += rv.z; r.w += rv.w;
            }
            if (RELU) {
                r.x = fmaxf(r.x, 0.f); r.y = fmaxf(r.y, 0.f);
                r.z = fmaxf(r.z, 0.f); r.w = fmaxf(r.w, 0.f);
            }
            *(float4*)(Ob + ro + n) = r;
        }
    }
}

// ---------------- attention scores: S[bh,i,j] = q[b,i,h,:] . k[b,j,h,:] ----------------
__global__ __launch_bounds__(256)
void scores_kernel(const float* __restrict__ q, const float* __restrict__ k,
                   float* __restrict__ sc) {
    int bh = blockIdx.z;
    int b = bh >> 4, h = bh & 15;
    int it = blockIdx.y, jt = blockIdx.x;
    __shared__ float qs[16][68], ks[16][68];
    int tid = threadIdx.x;
    int tx = tid & 15, ty = tid >> 4;
    int lrow = tid >> 2;
    int lk = (tid & 3) * 4;
    const float* qb = q + ((long)(b * SEQ + it * 64)) * D_MODEL + h * HEAD_D;
    const float* kb = k + ((long)(b * SEQ + jt * 64)) * D_MODEL + h * HEAD_D;
    float c[4][4];
#pragma unroll
    for (int i = 0; i < 4; i++)
#pragma unroll
        for (int j = 0; j < 4; j++) c[i][j] = 0.f;

    for (int d0 = 0; d0 < HEAD_D; d0 += 16) {
        float4 qv = *(const float4*)(qb + (long)lrow * D_MODEL + d0 + lk);
        float4 kv = *(const float4*)(kb + (long)lrow * D_MODEL + d0 + lk);
        __syncthreads();
        qs[lk + 0][lrow] = qv.x; qs[lk + 1][lrow] = qv.y;
        qs[lk + 2][lrow] = qv.z; qs[lk + 3][lrow] = qv.w;
        ks[lk + 0][lrow] = kv.x; ks[lk + 1][lrow] = kv.y;
        ks[lk + 2][lrow] = kv.z; ks[lk + 3][lrow] = kv.w;
        __syncthreads();
#pragma unroll
        for (int kk = 0; kk < 16; kk++) {
            float a[4], bb[4];
            *(float4*)&a[0]  = *(const float4*)&qs[kk][ty * 4];
            *(float4*)&bb[0] = *(const float4*)&ks[kk][tx * 4];
#pragma unroll
            for (int i = 0; i < 4; i++)
#pragma unroll
                for (int j = 0; j < 4; j++)
                    c[i][j] = fmaf(a[i], bb[j], c[i][j]);
        }
    }
    long base = (long)bh * SEQ * SEQ;
#pragma unroll
    for (int i = 0; i < 4; i++) {
        long ro = base + (long)(it * 64 + ty * 4 + i) * SEQ + jt * 64 + tx * 4;
        float4 r = make_float4(c[i][0], c[i][1], c[i][2], c[i][3]);
        *(float4*)(sc + ro) = r;
    }
}

// ---------------- row softmax over 512 ----------------
__global__ __launch_bounds__(128)
void softmax_kernel(float* __restrict__ sc) {
    __shared__ float redM[4], redS[4];
    float* row = sc + (size_t)blockIdx.x * SEQ;
    float v[4]; float m = -1e30f;
#pragma unroll
    for (int i = 0; i < 4; i++) { v[i] = row[threadIdx.x + 128 * i]; m = fmaxf(m, v[i]); }
#pragma unroll
    for (int o = 16; o; o >>= 1) m = fmaxf(m, __shfl_xor_sync(~0u, m, o));
    if ((threadIdx.x & 31) == 0) redM[threadIdx.x >> 5] = m;
    __syncthreads();
    m = fmaxf(fmaxf(redM[0], redM[1]), fmaxf(redM[2], redM[3]));
    float s = 0.f;
#pragma unroll
    for (int i = 0; i < 4; i++) { v[i] = expf(v[i] - m); s += v[i]; }
#pragma unroll
    for (int o = 16; o; o >>= 1) s += __shfl_xor_sync(~0u, s, o);
    if ((threadIdx.x & 31) == 0) redS[threadIdx.x >> 5] = s;
    __syncthreads();
    s = redS[0] + redS[1] + redS[2] + redS[3];
    float inv = 1.f / s;
#pragma unroll
    for (int i = 0; i < 4; i++) row[threadIdx.x + 128 * i] = v[i] * inv;
}

// ---------------- PV: O[b,i,h,:] = sum_j P[bh,i,j] * v[b,j,h,:] ----------------
__global__ __launch_bounds__(256)
void pv_kernel(const float* __restrict__ p, const float* __restrict__ v,
               float* __restrict__ o) {
    int bh = blockIdx.y;
    int b = bh >> 4, h = bh & 15;
    int it = blockIdx.x;
    __shared__ float ps[16][68], vs[16][68];
    int tid = threadIdx.x;
    int tx = tid & 15, ty = tid >> 4;
    int lrow = tid >> 2;
    int lk = (tid & 3) * 4;
    int vk = tid >> 4;           // 0..15
    int vd = (tid & 15) * 4;     // 0..60
    const float* pb = p + ((long)bh * SEQ + it * 64) * SEQ;
    const float* vb = v + (long)(b * SEQ) * D_MODEL + h * HEAD_D;
    float c[4][4];
#pragma unroll
    for (int i = 0; i < 4; i++)
#pragma unroll
        for (int j = 0; j < 4; j++) c[i][j] = 0.f;

    for (int kc = 0; kc < SEQ; kc += 16) {
        float4 pv4 = *(const float4*)(pb + (long)lrow * SEQ + kc + lk);
        float4 vv4 = *(const float4*)(vb + (long)(kc + vk) * D_MODEL + vd);
        __syncthreads();
        ps[lk + 0][lrow] = pv4.x; ps[lk + 1][lrow] = pv4.y;
        ps[lk + 2][lrow] = pv4.z; ps[lk + 3][lrow] = pv4.w;
        *(float4*)&vs[vk][vd] = vv4;
        __syncthreads();
#pragma unroll
        for (int kk = 0; kk < 16; kk++) {
            float a[4], bb[4];
            *(float4*)&a[0]  = *(const float4*)&ps[kk][ty * 4];
            *(float4*)&bb[0] = *(const float4*)&vs[kk][tx * 4];
#pragma unroll
            for (int i = 0; i < 4; i++)
#pragma unroll
                for (int j = 0; j < 4; j++)
                    c[i][j] = fmaf(a[i], bb[j], c[i][j]);
        }
    }
#pragma unroll
    for (int i = 0; i < 4; i++) {
        long ro = (long)(b * SEQ + it * 64 + ty * 4 + i) * D_MODEL + h * HEAD_D + tx * 4;
        float4 r = make_float4(c[i][0], c[i][1], c[i][2], c[i][3]);
        *(float4*)(o + ro) = r;
    }
}

// ---------------- router: logits, softmax(8), top1/top2, pre-norm gates ----------------
__global__ __launch_bounds__(256)
void router_kernel(const float* __restrict__ h2, const float* __restrict__ wr) {
    int t = blockIdx.x * 8 + (threadIdx.x >> 5);
    int lane = threadIdx.x & 31;
    const float* xr = h2 + (long)t * D_MODEL;
    float acc[8];
#pragma unroll
    for (int e = 0; e < 8; e++) acc[e] = 0.f;
    for (int i = lane; i < D_MODEL; i += 32) {
        float xv = xr[i];
        const float* w = wr + i * 8;
#pragma unroll
        for (int e = 0; e < 8; e++) acc[e] = fmaf(xv, w[e], acc[e]);
    }
#pragma unroll
    for (int o = 16; o; o >>= 1)
#pragma unroll
        for (int e = 0; e < 8; e++) acc[e] += __shfl_xor_sync(~0u, acc[e], o);
    if (lane == 0) {
        float m = acc[0];
        int t1 = 0;
#pragma unroll
        for (int e = 1; e < 8; e++) if (acc[e] > m) { m = acc[e]; t1 = e; }
        float s = 0.f;
        float pr[8];
#pragma unroll
        for (int e = 0; e < 8; e++) { pr[e] = expf(acc[e] - m); s += pr[e]; }
        float inv = 1.f / s;
        // top2 = argmax over logits excluding top1
        float m2 = -1e30f;
        int t2 = 0;
#pragma unroll
        for (int e = 0; e < 8; e++) {
            if (e == t1) continue;
            if (acc[e] > m2) { m2 = acc[e]; t2 = e; }
        }
        g_top1[t] = t1; g_top2[t] = t2;
        g_p1[t] = pr[t1] * inv;
        g_p2[t] = pr[t2] * inv;
    }
}

// ---------------- capacity scan + dispatch + gate normalization (single block) ----------------
__global__ __launch_bounds__(256)
void scan_kernel() {
    int tid = threadIdx.x;
    for (int i = tid; i < NEXP * CAPV; i += 256) g_disp[i] = 0;
    __syncthreads();
    int e = tid >> 5;
    int lane = tid & 31;
    unsigned lt = (1u << lane) - 1u;
    int base = 0;
    for (int c0 = 0; c0 < N_TOK; c0 += 32) {
        int t = c0 + lane;
        bool f = (g_top1[t] == e);
        unsigned msk = __ballot_sync(~0u, f);
        if (f) {
            int loc = base + __popc(msk & lt);
            if (loc < CAPV) { g_s1[t] = loc; g_disp[e * CAPV + loc] = t; }
            else g_s1[t] = -1;
        }
        base += __popc(msk);
    }
    // loc2 continues from total (uncapped) top1 count
    for (int c0 = 0; c0 < N_TOK; c0 += 32) {
        int t = c0 + lane;
        bool f = (g_top2[t] == e);
        unsigned msk = __ballot_sync(~0u, f);
        if (f) {
            int loc = base + __popc(msk & lt);
            if (loc < CAPV) { g_s2[t] = loc; g_disp[e * CAPV + loc] = t; }
            else g_s2[t] = -1;
        }
        base += __popc(msk);
    }
    __syncthreads();
    for (int t = tid; t < N_TOK; t += 256) {
        float t1 = (g_s1[t] >= 0) ? g_p1[t] : 0.f;
        float t2 = (g_s2[t] >= 0) ? g_p2[t] : 0.f;
        float den = fmaxf(t1 + t2, 1.1920929e-7f);
        g_g1[t] = t1 / den;
        g_g2[t] = t2 / den;
    }
}

// ---------------- combine: out[t] += g1*y[e1,s1] + g2*y[e2,s2] ----------------
__global__ __launch_bounds__(256)
void combine_kernel(float* __restrict__ out) {
    int t = blockIdx.x;
    int s1 = g_s1[t], s2 = g_s2[t];
    float g1 = g_g1[t], g2 = g_g2[t];
    const float* y1 = (s1 >= 0) ? g_y + ((long)g_top1[t] * CAPV + s1) * D_MODEL : 0;
    const float* y2 = (s2 >= 0) ? g_y + ((long)g_top2[t] * CAPV + s2) * D_MODEL : 0;
    long ro = (long)t * D_MODEL;
#pragma unroll
    for (int i = 0; i < 4; i++) {
        int d = threadIdx.x + 256 * i;
        float a = out[ro + d];
        if (y1) a = fmaf(g1, y1[d], a);
        if (y2) a = fmaf(g2, y2[d], a);
        out[ro + d] = a;
    }
}

// ---------------- launch ----------------
extern "C" void kernel_launch(void* const* d_in, const int* in_sizes, int n_in,
                              void* d_out, int out_size) {
    const float* x    = (const float*)d_in[0];
    const float* wq   = (const float*)d_in[1];
    const float* bq   = (const float*)d_in[2];
    const float* wk   = (const float*)d_in[3];
    const float* bk   = (const float*)d_in[4];
    const float* wv   = (const float*)d_in[5];
    const float* bv   = (const float*)d_in[6];
    const float* wo   = (const float*)d_in[7];
    const float* bo   = (const float*)d_in[8];
    const float* ln1g = (const float*)d_in[9];
    const float* ln1b = (const float*)d_in[10];
    const float* ln2g = (const float*)d_in[11];
    const float* ln2b = (const float*)d_in[12];
    const float* wr   = (const float*)d_in[13];
    const float* w1   = (const float*)d_in[14];
    const float* b1   = (const float*)d_in[15];
    const float* w2   = (const float*)d_in[16];
    const float* b2   = (const float*)d_in[17];
    float* out = (float*)d_out;

    float* h1;   cudaGetSymbolAddress((void**)&h1,   g_h1);
    float* q;    cudaGetSymbolAddress((void**)&q,    g_q);
    float* k;    cudaGetSymbolAddress((void**)&k,    g_k);
    float* v;    cudaGetSymbolAddress((void**)&v,    g_v);
    float* attn; cudaGetSymbolAddress((void**)&attn, g_attn);
    float* h2;   cudaGetSymbolAddress((void**)&h2,   g_h2);
    float* sc;   cudaGetSymbolAddress((void**)&sc,   g_sc);
    float* hmid; cudaGetSymbolAddress((void**)&hmid, g_hmid);
    float* y;    cudaGetSymbolAddress((void**)&y,    g_y);
    int*   disp; cudaGetSymbolAddress((void**)&disp, g_disp);

    const float qscale = 0.125f;  // HEAD_D^-0.5

    // 1) LN1
    ln_kernel<<<N_TOK, 256>>>(x, ln1g, ln1b, h1);
    // 2) Q, K, V projections
    dim3 gQKV(D_MODEL / 128, N_TOK / 128, 1);
    gemm128<false, false><<<gQKV, 256>>>(h1, wq, bq, nullptr, q, D_MODEL, D_MODEL, qscale, nullptr, 0, 0, 0, 0);
    gemm128<false, false><<<gQKV, 256>>>(h1, wk, bk, nullptr, k, D_MODEL, D_MODEL, 1.f,    nullptr, 0, 0, 0, 0);
    gemm128<false, false><<<gQKV, 256>>>(h1, wv, bv, nullptr, v, D_MODEL, D_MODEL, 1.f,    nullptr, 0, 0, 0, 0);
    // 3) scores
    scores_kernel<<<dim3(SEQ / 64, SEQ / 64, NB * N_HEADS), 256>>>(q, k, sc);
    // 4) softmax
    softmax_kernel<<<NB * N_HEADS * SEQ, 128>>>(sc);
    // 5) PV
    pv_kernel<<<dim3(SEQ / 64, NB * N_HEADS), 256>>>(sc, v, attn);
    // 6) O projection + residual x -> out
    gemm128<false, false><<<gQKV, 256>>>(attn, wo, bo, x, out, D_MODEL, D_MODEL, 1.f, nullptr, 0, 0, 0, 0);
    // 7) LN2
    ln_kernel<<<N_TOK, 256>>>(out, ln2g, ln2b, h2);
    // 8) router
    router_kernel<<<N_TOK / 8, 256>>>(h2, wr);
    // 9) capacity scan + dispatch
    scan_kernel<<<1, 256>>>();
    // 10) expert FFN layer 1 (gathered rows, relu)
    dim3 gF1(FFN_D / 128, CAPV / 128, NEXP);
    gemm128<true, true><<<gF1, 256>>>(h2, w1, b1, nullptr, hmid, D_MODEL, FFN_D, 1.f,
                                      disp, 0, (long)D_MODEL * FFN_D, FFN_D, (long)CAPV * FFN_D);
    // 11) expert FFN layer 2 (scaled by 1 - moe_token_dropout = 0.8)
    dim3 gF2(D_MODEL / 128, CAPV / 128, NEXP);
    gemm128<false, false><<<gF2, 256>>>(hmid, w2, b2, nullptr, y, FFN_D, D_MODEL, 0.8f,
                                        nullptr, (long)CAPV * FFN_D, (long)FFN_D * D_MODEL, D_MODEL, (long)CAPV * D_MODEL);
    // 12) combine gates
    combine_kernel<<<N_TOK, 256>>>(out);
}

// round 3
// speedup vs baseline: 1.8717x; 1.8717x over previous
#include <cuda_runtime.h>
#include <cuda_bf16.h>
#include <cstdint>

#define D_MODEL 1024
#define N_TOK   2048
#define N_HEADS 16
#define HEAD_D  64
#define SEQ     512
#define NB      4
#define FFN_D   4096
#define NEXP    8
#define CAPV    512

// ================= device scratch =================
__device__ float g_h1  [N_TOK * D_MODEL];
__device__ float g_q   [N_TOK * D_MODEL];
__device__ float g_k   [N_TOK * D_MODEL];
__device__ float g_v   [N_TOK * D_MODEL];
__device__ float g_attn[N_TOK * D_MODEL];
__device__ float g_h2  [N_TOK * D_MODEL];
__device__ float g_sc  [(size_t)NB * N_HEADS * SEQ * SEQ];
__device__ float g_mid [(size_t)NEXP * CAPV * FFN_D];
__device__ float g_y   [(size_t)NEXP * CAPV * D_MODEL];
__device__ int   g_top1[N_TOK], g_top2[N_TOK];
__device__ float g_p1[N_TOK], g_p2[N_TOK];
__device__ int   g_s1[N_TOK], g_s2[N_TOK];
__device__ float g_g1[N_TOK], g_g2[N_TOK];
__device__ int   g_disp[NEXP * CAPV];

// ================= mma / ldmatrix helpers (base sm_103 target safe) =================
__device__ __forceinline__ uint32_t smem_u32(const void* p) {
    uint32_t a;
    asm("{ .reg .u64 t; cvta.to.shared.u64 t, %1; cvt.u32.u64 %0, t; }" : "=r"(a) : "l"(p));
    return a;
}
__device__ __forceinline__ void ldsm_x4(uint32_t* r, uint32_t addr) {
    asm volatile("ldmatrix.sync.aligned.m8n8.x4.shared.b16 {%0,%1,%2,%3}, [%4];"
        : "=r"(r[0]), "=r"(r[1]), "=r"(r[2]), "=r"(r[3]) : "r"(addr));
}
__device__ __forceinline__ void ldsm_x4t(uint32_t* r, uint32_t addr) {
    asm volatile("ldmatrix.sync.aligned.m8n8.x4.trans.shared.b16 {%0,%1,%2,%3}, [%4];"
        : "=r"(r[0]), "=r"(r[1]), "=r"(r[2]), "=r"(r[3]) : "r"(addr));
}
__device__ __forceinline__ void mma16816(float* c, const uint32_t* a, uint32_t b0, uint32_t b1) {
    asm volatile(
        "mma.sync.aligned.m16n8k16.row.col.f32.bf16.bf16.f32 "
        "{%0,%1,%2,%3}, {%4,%5,%6,%7}, {%8,%9}, {%0,%1,%2,%3};"
        : "+f"(c[0]), "+f"(c[1]), "+f"(c[2]), "+f"(c[3])
        : "r"(a[0]), "r"(a[1]), "r"(a[2]), "r"(a[3]), "r"(b0), "r"(b1));
}
__device__ __forceinline__ void split2(float x, uint16_t& h, uint16_t& l) {
    __nv_bfloat16 hb = __float2bfloat16(x);
    float r = x - __bfloat162float(hb);
    h = __bfloat16_as_ushort(hb);
    l = __bfloat16_as_ushort(__float2bfloat16(r));
}
__device__ __forceinline__ void cvt4(float4 v, uint2& hi, uint2& lo) {
    uint16_t h0, h1, h2, h3, l0, l1, l2, l3;
    split2(v.x, h0, l0); split2(v.y, h1, l1);
    split2(v.z, h2, l2); split2(v.w, h3, l3);
    hi.x = (uint32_t)h0 | ((uint32_t)h1 << 16);
    hi.y = (uint32_t)h2 | ((uint32_t)h3 << 16);
    lo.x = (uint32_t)l0 | ((uint32_t)l1 << 16);
    lo.y = (uint32_t)l2 | ((uint32_t)l3 << 16);
}

// ================= split-bf16 HMMA GEMM: CTA 128x128, Kc=32, 8 warps of 64x32 =================
// A fp32 [M,K] row-major (optionally row-gathered), B fp32 [K,N] row-major (native weights).
#define KC 32
#define SM_AH 0
#define SM_AL 10240        /* 128 rows * 40 elems * 2B */
#define SM_BH 20480
#define SM_BL 28672        /* 32 rows * 256B */
#define BUF_BYTES 36864
#define GEMM_SMEM (2 * BUF_BYTES)

template <bool RELU, bool GATHER, bool MULTI>
__global__ __launch_bounds__(256, 1)
void gemm_mma(const float* __restrict__ A,
              const float* __restrict__ B0, const float* __restrict__ B1, const float* __restrict__ B2,
              const float* __restrict__ bi0, const float* __restrict__ bi1, const float* __restrict__ bi2,
              float* __restrict__ o0, float* __restrict__ o1, float* __restrict__ o2,
              float s0, float s1, float s2,
              const float* __restrict__ resid,
              const int* __restrict__ gather,
              int K, int N,
              long aStride, long bStride, long biStride, long oStride) {
    extern __shared__ char sm[];
    uint32_t sb = smem_u32(sm);
    int tid = threadIdx.x, wid = tid >> 5, lane = tid & 31;
    int z = blockIdx.z;
    int m0 = blockIdx.y * 128, n0 = blockIdx.x * 128;

    const float* B; const float* bi; float* O; float scale;
    if (MULTI) {
        B = (z == 0) ? B0 : (z == 1) ? B1 : B2;
        bi = (z == 0) ? bi0 : (z == 1) ? bi1 : bi2;
        O = (z == 0) ? o0 : (z == 1) ? o1 : o2;
        scale = (z == 0) ? s0 : (z == 1) ? s1 : s2;
    } else {
        B = B0 + (long)z * bStride;
        bi = bi0 + (long)z * biStride;
        O = o0 + (long)z * oStride;
        scale = s0;
    }
    const float* Az = A + (MULTI ? 0 : (long)z * aStride);
    const int* gz = GATHER ? (gather + z * CAPV) : nullptr;

    // global load mapping
    long aRowG[4];
    int aColG = (tid & 7) * 4;
    int sAoff[4], sBoff[4];
#pragma unroll
    for (int i = 0; i < 4; i++) {
        int r = (tid + 256 * i) >> 3;
        long grow = GATHER ? (long)gz[m0 + r] : (long)(m0 + r);
        aRowG[i] = grow * K + aColG;
        sAoff[i] = r * 80 + (tid & 7) * 8;
        int kr = (tid >> 5) + 8 * i;
        sBoff[i] = kr * 256 + (((tid & 31) * 8) ^ ((kr & 7) << 4));
    }
    int bRow0 = tid >> 5;
    int bColG = n0 + (tid & 31) * 4;

    float c[4][4][4];
#pragma unroll
    for (int mt = 0; mt < 4; mt++)
#pragma unroll
        for (int nt = 0; nt < 4; nt++)
#pragma unroll
            for (int f = 0; f < 4; f++) c[mt][nt][f] = 0.f;

    int wm = wid >> 2;   // 0..1 -> m 64
    int wn = wid & 3;    // 0..3 -> n 32
    int aRowOff = (lane & 7) + ((lane >> 3) & 1) * 8;
    int aColSel = ((lane >> 4) & 1) * 16;
    int bKoff = (lane & 7) + ((lane >> 3) & 1) * 8;
    int bN8 = ((lane >> 4) & 1) * 8;

    float4 av[4], bv[4];
#pragma unroll
    for (int i = 0; i < 4; i++) av[i] = *(const float4*)(Az + aRowG[i]);
#pragma unroll
    for (int i = 0; i < 4; i++) bv[i] = *(const float4*)(B + (long)(bRow0 + 8 * i) * N + bColG);

    int nCh = K >> 5;
    for (int ch = 0; ch < nCh; ch++) {
        char* smb = sm + (ch & 1) * BUF_BYTES;
        uint32_t sbuf = sb + (ch & 1) * BUF_BYTES;
        __syncthreads();
#pragma unroll
        for (int i = 0; i < 4; i++) {
            uint2 hi, lo;
            cvt4(av[i], hi, lo);
            *(uint2*)(smb + SM_AH + sAoff[i]) = hi;
            *(uint2*)(smb + SM_AL + sAoff[i]) = lo;
        }
#pragma unroll
        for (int i = 0; i < 4; i++) {
            uint2 hi, lo;
            cvt4(bv[i], hi, lo);
            *(uint2*)(smb + SM_BH + sBoff[i]) = hi;
            *(uint2*)(smb + SM_BL + sBoff[i]) = lo;
        }
        __syncthreads();
        if (ch + 1 < nCh) {
            int k0 = (ch + 1) << 5;
#pragma unroll
            for (int i = 0; i < 4; i++) av[i] = *(const float4*)(Az + aRowG[i] + k0);
#pragma unroll
            for (int i = 0; i < 4; i++)
                bv[i] = *(const float4*)(B + (long)(k0 + bRow0 + 8 * i) * N + bColG);
        }
#pragma unroll
        for (int ks = 0; ks < 2; ks++) {
            uint32_t ah[4][4], al[4][4];
#pragma unroll
            for (int mt = 0; mt < 4; mt++) {
                uint32_t ro = (wm * 64 + mt * 16 + aRowOff) * 80 + ks * 32 + aColSel;
                ldsm_x4(ah[mt], sbuf + SM_AH + ro);
                ldsm_x4(al[mt], sbuf + SM_AL + ro);
            }
            uint32_t bh[2][4], bl[2][4];
#pragma unroll
            for (int nb = 0; nb < 2; nb++) {
                int kk = ks * 16 + bKoff;
                int nn = wn * 32 + nb * 16 + bN8;
                uint32_t off = kk * 256 + ((nn * 2) ^ ((kk & 7) << 4));
                ldsm_x4t(bh[nb], sbuf + SM_BH + off);
                ldsm_x4t(bl[nb], sbuf + SM_BL + off);
            }
#pragma unroll
            for (int mt = 0; mt < 4; mt++)
#pragma unroll
                for (int nt = 0; nt < 4; nt++) {
                    const uint32_t* bp = &bh[nt >> 1][(nt & 1) * 2];
                    const uint32_t* lp = &bl[nt >> 1][(nt & 1) * 2];
                    mma16816(c[mt][nt], ah[mt], bp[0], bp[1]);
                    mma16816(c[mt][nt], ah[mt], lp[0], lp[1]);
                    mma16816(c[mt][nt], al[mt], bp[0], bp[1]);
                }
        }
    }

    // epilogue
    int r0 = m0 + wm * 64 + (lane >> 2);
    int col0 = n0 + wn * 32 + (lane & 3) * 2;
#pragma unroll
    for (int mt = 0; mt < 4; mt++) {
#pragma unroll
        for (int nt = 0; nt < 4; nt++) {
            int row = r0 + mt * 16;
            int cn = col0 + nt * 8;
            float2 bb = *(const float2*)(bi + cn);
            float v0x = (c[mt][nt][0] + bb.x) * scale;
            float v0y = (c[mt][nt][1] + bb.y) * scale;
            float v1x = (c[mt][nt][2] + bb.x) * scale;
            float v1y = (c[mt][nt][3] + bb.y) * scale;
            if (resid) {
                float2 ra = *(const float2*)(resid + (long)row * N + cn);
                float2 rb = *(const float2*)(resid + (long)(row + 8) * N + cn);
                v0x += ra.x; v0y += ra.y; v1x += rb.x; v1y += rb.y;
            }
            if (RELU) {
                v0x = fmaxf(v0x, 0.f); v0y = fmaxf(v0y, 0.f);
                v1x = fmaxf(v1x, 0.f); v1y = fmaxf(v1y, 0.f);
            }
            *(float2*)(O + (long)row * N + cn) = make_float2(v0x, v0y);
            *(float2*)(O + (long)(row + 8) * N + cn) = make_float2(v1x, v1y);
        }
    }
}

// ================= LayerNorm =================
__global__ void ln_kernel(const float* __restrict__ x, const float* __restrict__ gam,
                          const float* __restrict__ bet, float* __restrict__ out) {
    __shared__ float redA[8], redB[8];
    int t = blockIdx.x;
    const float* xr = x + (size_t)t * D_MODEL;
    float v[4]; float s = 0.f;
#pragma unroll
    for (int i = 0; i < 4; i++) { v[i] = xr[threadIdx.x + 256 * i]; s += v[i]; }
#pragma unroll
    for (int o = 16; o; o >>= 1) s += __shfl_xor_sync(~0u, s, o);
    if ((threadIdx.x & 31) == 0) redA[threadIdx.x >> 5] = s;
    __syncthreads();
    if (threadIdx.x == 0) { float r = 0.f; for (int i = 0; i < 8; i++) r += redA[i]; redA[0] = r; }
    __syncthreads();
    float mu = redA[0] * (1.f / D_MODEL);
    float s2 = 0.f;
#pragma unroll
    for (int i = 0; i < 4; i++) { float d = v[i] - mu; s2 += d * d; }
#pragma unroll
    for (int o = 16; o; o >>= 1) s2 += __shfl_xor_sync(~0u, s2, o);
    if ((threadIdx.x & 31) == 0) redB[threadIdx.x >> 5] = s2;
    __syncthreads();
    if (threadIdx.x == 0) { float r = 0.f; for (int i = 0; i < 8; i++) r += redB[i]; redB[0] = r; }
    __syncthreads();
    float rstd = rsqrtf(redB[0] * (1.f / D_MODEL) + 1e-5f);
    float* orow = out + (size_t)t * D_MODEL;
#pragma unroll
    for (int i = 0; i < 4; i++) {
        int c = threadIdx.x + 256 * i;
        orow[c] = (v[i] - mu) * rstd * gam[c] + bet[c];
    }
}

// ================= attention =================
__global__ __launch_bounds__(256)
void scores_kernel(const float* __restrict__ q, const float* __restrict__ k,
                   float* __restrict__ sc) {
    int bh = blockIdx.z;
    int b = bh >> 4, h = bh & 15;
    int it = blockIdx.y, jt = blockIdx.x;
    __shared__ float qs[16][68], ks[16][68];
    int tid = threadIdx.x;
    int tx = tid & 15, ty = tid >> 4;
    int lrow = tid >> 2;
    int lk = (tid & 3) * 4;
    const float* qb = q + ((long)(b * SEQ + it * 64)) * D_MODEL + h * HEAD_D;
    const float* kb = k + ((long)(b * SEQ + jt * 64)) * D_MODEL + h * HEAD_D;
    float c[4][4];
#pragma unroll
    for (int i = 0; i < 4; i++)
#pragma unroll
        for (int j = 0; j < 4; j++) c[i][j] = 0.f;
    for (int d0 = 0; d0 < HEAD_D; d0 += 16) {
        float4 qv = *(const float4*)(qb + (long)lrow * D_MODEL + d0 + lk);
        float4 kv = *(const float4*)(kb + (long)lrow * D_MODEL + d0 + lk);
        __syncthreads();
        qs[lk + 0][lrow] = qv.x; qs[lk + 1][lrow] = qv.y;
        qs[lk + 2][lrow] = qv.z; qs[lk + 3][lrow] = qv.w;
        ks[lk + 0][lrow] = kv.x; ks[lk + 1][lrow] = kv.y;
        ks[lk + 2][lrow] = kv.z; ks[lk + 3][lrow] = kv.w;
        __syncthreads();
#pragma unroll
        for (int kk = 0; kk < 16; kk++) {
            float a[4], bb[4];
            *(float4*)&a[0]  = *(const float4*)&qs[kk][ty * 4];
            *(float4*)&bb[0] = *(const float4*)&ks[kk][tx * 4];
#pragma unroll
            for (int i = 0; i < 4; i++)
#pragma unroll
                for (int j = 0; j < 4; j++)
                    c[i][j] = fmaf(a[i], bb[j], c[i][j]);
        }
    }
    long base = (long)bh * SEQ * SEQ;
#pragma unroll
    for (int i = 0; i < 4; i++) {
        long ro = base + (long)(it * 64 + ty * 4 + i) * SEQ + jt * 64 + tx * 4;
        *(float4*)(sc + ro) = make_float4(c[i][0], c[i][1], c[i][2], c[i][3]);
    }
}

__global__ __launch_bounds__(128)
void softmax_kernel(float* __restrict__ sc) {
    __shared__ float redM[4], redS[4];
    float* row = sc + (size_t)blockIdx.x * SEQ;
    float v[4]; float m = -1e30f;
#pragma unroll
    for (int i = 0; i < 4; i++) { v[i] = row[threadIdx.x + 128 * i]; m = fmaxf(m, v[i]); }
#pragma unroll
    for (int o = 16; o; o >>= 1) m = fmaxf(m, __shfl_xor_sync(~0u, m, o));
    if ((threadIdx.x & 31) == 0) redM[threadIdx.x >> 5] = m;
    __syncthreads();
    m = fmaxf(fmaxf(redM[0], redM[1]), fmaxf(redM[2], redM[3]));
    float s = 0.f;
#pragma unroll
    for (int i = 0; i < 4; i++) { v[i] = expf(v[i] - m); s += v[i]; }
#pragma unroll
    for (int o = 16; o; o >>= 1) s += __shfl_xor_sync(~0u, s, o);
    if ((threadIdx.x & 31) == 0) redS[threadIdx.x >> 5] = s;
    __syncthreads();
    s = redS[0] + redS[1] + redS[2] + redS[3];
    float inv = 1.f / s;
#pragma unroll
    for (int i = 0; i < 4; i++) row[threadIdx.x + 128 * i] = v[i] * inv;
}

__global__ __launch_bounds__(256)
void pv_kernel(const float* __restrict__ p, const float* __restrict__ v,
               float* __restrict__ o) {
    int bh = blockIdx.y;
    int b = bh >> 4, h = bh & 15;
    int it = blockIdx.x;
    __shared__ float ps[16][68], vs[16][68];
    int tid = threadIdx.x;
    int tx = tid & 15, ty = tid >> 4;
    int lrow = tid >> 2;
    int lk = (tid & 3) * 4;
    int vk = tid >> 4;
    int vd = (tid & 15) * 4;
    const float* pb = p + ((long)bh * SEQ + it * 64) * SEQ;
    const float* vb = v + (long)(b * SEQ) * D_MODEL + h * HEAD_D;
    float c[4][4];
#pragma unroll
    for (int i = 0; i < 4; i++)
#pragma unroll
        for (int j = 0; j < 4; j++) c[i][j] = 0.f;
    for (int kc = 0; kc < SEQ; kc += 16) {
        float4 pv4 = *(const float4*)(pb + (long)lrow * SEQ + kc + lk);
        float4 vv4 = *(const float4*)(vb + (long)(kc + vk) * D_MODEL + vd);
        __syncthreads();
        ps[lk + 0][lrow] = pv4.x; ps[lk + 1][lrow] = pv4.y;
        ps[lk + 2][lrow] = pv4.z; ps[lk + 3][lrow] = pv4.w;
        *(float4*)&vs[vk][vd] = vv4;
        __syncthreads();
#pragma unroll
        for (int kk = 0; kk < 16; kk++) {
            float a[4], bb[4];
            *(float4*)&a[0]  = *(const float4*)&ps[kk][ty * 4];
            *(float4*)&bb[0] = *(const float4*)&vs[kk][tx * 4];
#pragma unroll
            for (int i = 0; i < 4; i++)
#pragma unroll
                for (int j = 0; j < 4; j++)
                    c[i][j] = fmaf(a[i], bb[j], c[i][j]);
        }
    }
#pragma unroll
    for (int i = 0; i < 4; i++) {
        long ro = (long)(b * SEQ + it * 64 + ty * 4 + i) * D_MODEL + h * HEAD_D + tx * 4;
        *(float4*)(o + ro) = make_float4(c[i][0], c[i][1], c[i][2], c[i][3]);
    }
}

// ================= router / scan / combine =================
__global__ __launch_bounds__(256)
void router_kernel(const float* __restrict__ h2, const float* __restrict__ wr) {
    int t = blockIdx.x * 8 + (threadIdx.x >> 5);
    int lane = threadIdx.x & 31;
    const float* xr = h2 + (long)t * D_MODEL;
    float acc[8];
#pragma unroll
    for (int e = 0; e < 8; e++) acc[e] = 0.f;
    for (int i = lane; i < D_MODEL; i += 32) {
        float xv = xr[i];
        const float* w = wr + i * 8;
#pragma unroll
        for (int e = 0; e < 8; e++) acc[e] = fmaf(xv, w[e], acc[e]);
    }
#pragma unroll
    for (int o = 16; o; o >>= 1)
#pragma unroll
        for (int e = 0; e < 8; e++) acc[e] += __shfl_xor_sync(~0u, acc[e], o);
    if (lane == 0) {
        float m = acc[0]; int t1 = 0;
#pragma unroll
        for (int e = 1; e < 8; e++) if (acc[e] > m) { m = acc[e]; t1 = e; }
        float s = 0.f, pr[8];
#pragma unroll
        for (int e = 0; e < 8; e++) { pr[e] = expf(acc[e] - m); s += pr[e]; }
        float inv = 1.f / s;
        float m2 = -1e30f; int t2 = 0;
#pragma unroll
        for (int e = 0; e < 8; e++) {
            if (e == t1) continue;
            if (acc[e] > m2) { m2 = acc[e]; t2 = e; }
        }
        g_top1[t] = t1; g_top2[t] = t2;
        g_p1[t] = pr[t1] * inv;
        g_p2[t] = pr[t2] * inv;
    }
}

__global__ __launch_bounds__(256)
void scan_kernel() {
    int tid = threadIdx.x;
    for (int i = tid; i < NEXP * CAPV; i += 256) g_disp[i] = 0;
    __syncthreads();
    int e = tid >> 5;
    int lane = tid & 31;
    unsigned lt = (1u << lane) - 1u;
    int base = 0;
    for (int c0 = 0; c0 < N_TOK; c0 += 32) {
        int t = c0 + lane;
        bool f = (g_top1[t] == e);
        unsigned msk = __ballot_sync(~0u, f);
        if (f) {
            int loc = base + __popc(msk & lt);
            if (loc < CAPV) { g_s1[t] = loc; g_disp[e * CAPV + loc] = t; }
            else g_s1[t] = -1;
        }
        base += __popc(msk);
    }
    for (int c0 = 0; c0 < N_TOK; c0 += 32) {
        int t = c0 + lane;
        bool f = (g_top2[t] == e);
        unsigned msk = __ballot_sync(~0u, f);
        if (f) {
            int loc = base + __popc(msk & lt);
            if (loc < CAPV) { g_s2[t] = loc; g_disp[e * CAPV + loc] = t; }
            else g_s2[t] = -1;
        }
        base += __popc(msk);
    }
    __syncthreads();
    for (int t = tid; t < N_TOK; t += 256) {
        float t1 = (g_s1[t] >= 0) ? g_p1[t] : 0.f;
        float t2 = (g_s2[t] >= 0) ? g_p2[t] : 0.f;
        float den = fmaxf(t1 + t2, 1.1920929e-7f);
        g_g1[t] = t1 / den;
        g_g2[t] = t2 / den;
    }
}

__global__ __launch_bounds__(256)
void combine_kernel(float* __restrict__ out) {
    int t = blockIdx.x;
    int s1 = g_s1[t], s2 = g_s2[t];
    float g1 = g_g1[t], g2 = g_g2[t];
    const float* y1 = (s1 >= 0) ? g_y + ((long)g_top1[t] * CAPV + s1) * D_MODEL : 0;
    const float* y2 = (s2 >= 0) ? g_y + ((long)g_top2[t] * CAPV + s2) * D_MODEL : 0;
    long ro = (long)t * D_MODEL;
#pragma unroll
    for (int i = 0; i < 4; i++) {
        int d = threadIdx.x + 256 * i;
        float a = out[ro + d];
        if (y1) a = fmaf(g1, y1[d], a);
        if (y2) a = fmaf(g2, y2[d], a);
        out[ro + d] = a;
    }
}

// ================= launch =================
extern "C" void kernel_launch(void* const* d_in, const int* in_sizes, int n_in,
                              void* d_out, int out_size) {
    const float* x    = (const float*)d_in[0];
    const float* wq   = (const float*)d_in[1];
    const float* bq   = (const float*)d_in[2];
    const float* wk   = (const float*)d_in[3];
    const float* bk   = (const float*)d_in[4];
    const float* wv   = (const float*)d_in[5];
    const float* bv   = (const float*)d_in[6];
    const float* wo   = (const float*)d_in[7];
    const float* bo   = (const float*)d_in[8];
    const float* ln1g = (const float*)d_in[9];
    const float* ln1b = (const float*)d_in[10];
    const float* ln2g = (const float*)d_in[11];
    const float* ln2b = (const float*)d_in[12];
    const float* wr   = (const float*)d_in[13];
    const float* w1   = (const float*)d_in[14];
    const float* b1   = (const float*)d_in[15];
    const float* w2   = (const float*)d_in[16];
    const float* b2   = (const float*)d_in[17];
    float* out = (float*)d_out;

    float *h1, *q, *k, *v, *attn, *h2, *sc, *mid, *y;
    int* disp;
    cudaGetSymbolAddress((void**)&h1,   g_h1);
    cudaGetSymbolAddress((void**)&q,    g_q);
    cudaGetSymbolAddress((void**)&k,    g_k);
    cudaGetSymbolAddress((void**)&v,    g_v);
    cudaGetSymbolAddress((void**)&attn, g_attn);
    cudaGetSymbolAddress((void**)&h2,   g_h2);
    cudaGetSymbolAddress((void**)&sc,   g_sc);
    cudaGetSymbolAddress((void**)&mid,  g_mid);
    cudaGetSymbolAddress((void**)&y,    g_y);
    cudaGetSymbolAddress((void**)&disp, g_disp);

    cudaFuncSetAttribute(gemm_mma<false, false, true>,
                         cudaFuncAttributeMaxDynamicSharedMemorySize, GEMM_SMEM);
    cudaFuncSetAttribute(gemm_mma<false, false, false>,
                         cudaFuncAttributeMaxDynamicSharedMemorySize, GEMM_SMEM);
    cudaFuncSetAttribute(gemm_mma<true, true, false>,
                         cudaFuncAttributeMaxDynamicSharedMemorySize, GEMM_SMEM);

    // 1) LN1
    ln_kernel<<<N_TOK, 256>>>(x, ln1g, ln1b, h1);

    // 2) QKV fused (z selects weight/bias/out/scale)
    gemm_mma<false, false, true><<<dim3(8, 16, 3), 256, GEMM_SMEM>>>(
        h1, wq, wk, wv, bq, bk, bv, q, k, v, 0.125f, 1.f, 1.f,
        nullptr, nullptr, 1024, 1024, 0, 0, 0, 0);

    // 3) attention
    scores_kernel<<<dim3(SEQ / 64, SEQ / 64, NB * N_HEADS), 256>>>(q, k, sc);
    softmax_kernel<<<NB * N_HEADS * SEQ, 128>>>(sc);
    pv_kernel<<<dim3(SEQ / 64, NB * N_HEADS), 256>>>(sc, v, attn);

    // 4) O projection + residual
    gemm_mma<false, false, false><<<dim3(8, 16, 1), 256, GEMM_SMEM>>>(
        attn, wo, nullptr, nullptr, bo, nullptr, nullptr, out, nullptr, nullptr,
        1.f, 0.f, 0.f, x, nullptr, 1024, 1024, 0, 0, 0, 0);

    // 5) LN2
    ln_kernel<<<N_TOK, 256>>>(out, ln2g, ln2b, h2);

    // 6) router + capacity scan
    router_kernel<<<N_TOK / 8, 256>>>(h2, wr);
    scan_kernel<<<1, 256>>>();

    // 7) FFN1: gathered A rows, relu
    gemm_mma<true, true, false><<<dim3(32, 4, 8), 256, GEMM_SMEM>>>(
        h2, w1, nullptr, nullptr, b1, nullptr, nullptr, mid, nullptr, nullptr,
        1.f, 0.f, 0.f, nullptr, disp, 1024, 4096,
        0, (long)D_MODEL * FFN_D, FFN_D, (long)CAPV * FFN_D);

    // 8) FFN2: *0.8 dropout scaling
    gemm_mma<false, false, false><<<dim3(8, 4, 8), 256, GEMM_SMEM>>>(
        mid, w2, nullptr, nullptr, b2, nullptr, nullptr, y, nullptr, nullptr,
        0.8f, 0.f, 0.f, nullptr, nullptr, 4096, 1024,
        (long)CAPV * FFN_D, (long)FFN_D * D_MODEL, D_MODEL, (long)CAPV * D_MODEL);

    // 9) combine
    combine_kernel<<<N_TOK, 256>>>(out);
}

// round 4
// speedup vs baseline: 2.1685x; 1.1586x over previous
#include <cuda_runtime.h>
#include <cuda_bf16.h>
#include <cstdint>

#define D_MODEL 1024
#define N_TOK   2048
#define N_HEADS 16
#define HEAD_D  64
#define SEQ     512
#define NB      4
#define FFN_D   4096
#define NEXP    8
#define CAPV    512

typedef __nv_bfloat16 bf16;

// ================= device scratch =================
__device__ bf16 g_wqh[1048576], g_wql[1048576];
__device__ bf16 g_wkh[1048576], g_wkl[1048576];
__device__ bf16 g_wvh[1048576], g_wvl[1048576];
__device__ bf16 g_woh[1048576], g_wol[1048576];
__device__ bf16 g_w1h[33554432], g_w1l[33554432];
__device__ bf16 g_w2h[33554432], g_w2l[33554432];
__device__ bf16 g_h1h[2097152], g_h1l[2097152];
__device__ bf16 g_h2h[2097152], g_h2l[2097152];
__device__ float g_h2[2097152];
__device__ bf16 g_qh[2097152], g_ql[2097152];
__device__ bf16 g_kh[2097152], g_kl[2097152];
__device__ bf16 g_vh[2097152], g_vl[2097152];
__device__ bf16 g_ath[2097152], g_atl[2097152];
__device__ bf16 g_midh[16777216], g_midl[16777216];
__device__ bf16 g_ph[16777216], g_pl[16777216];
__device__ float g_sc[16777216];
__device__ float g_y[4194304];
__device__ int   g_top1[N_TOK], g_top2[N_TOK];
__device__ float g_p1[N_TOK], g_p2[N_TOK];
__device__ int   g_s1[N_TOK], g_s2[N_TOK];
__device__ float g_g1[N_TOK], g_g2[N_TOK];
__device__ int   g_disp[NEXP * CAPV];

// ================= helpers =================
__device__ __forceinline__ uint32_t smem_u32(const void* p) {
    uint32_t a;
    asm("{ .reg .u64 t; cvta.to.shared.u64 t, %1; cvt.u32.u64 %0, t; }" : "=r"(a) : "l"(p));
    return a;
}
__device__ __forceinline__ void ldsm_x4(uint32_t* r, uint32_t addr) {
    asm volatile("ldmatrix.sync.aligned.m8n8.x4.shared.b16 {%0,%1,%2,%3}, [%4];"
        : "=r"(r[0]), "=r"(r[1]), "=r"(r[2]), "=r"(r[3]) : "r"(addr));
}
__device__ __forceinline__ void ldsm_x4t(uint32_t* r, uint32_t addr) {
    asm volatile("ldmatrix.sync.aligned.m8n8.x4.trans.shared.b16 {%0,%1,%2,%3}, [%4];"
        : "=r"(r[0]), "=r"(r[1]), "=r"(r[2]), "=r"(r[3]) : "r"(addr));
}
__device__ __forceinline__ void mma16816(float* c, const uint32_t* a, uint32_t b0, uint32_t b1) {
    asm volatile(
        "mma.sync.aligned.m16n8k16.row.col.f32.bf16.bf16.f32 "
        "{%0,%1,%2,%3}, {%4,%5,%6,%7}, {%8,%9}, {%0,%1,%2,%3};"
        : "+f"(c[0]), "+f"(c[1]), "+f"(c[2]), "+f"(c[3])
        : "r"(a[0]), "r"(a[1]), "r"(a[2]), "r"(a[3]), "r"(b0), "r"(b1));
}
__device__ __forceinline__ void split2(float x, uint16_t& h, uint16_t& l) {
    __nv_bfloat16 hb = __float2bfloat16(x);
    float r = x - __bfloat162float(hb);
    h = __bfloat16_as_ushort(hb);
    l = __bfloat16_as_ushort(__float2bfloat16(r));
}
__device__ __forceinline__ void pack2(float x, float y, uint32_t& hi, uint32_t& lo) {
    uint16_t hx, lx, hy, ly;
    split2(x, hx, lx); split2(y, hy, ly);
    hi = (uint32_t)hx | ((uint32_t)hy << 16);
    lo = (uint32_t)lx | ((uint32_t)ly << 16);
}

// ================= weight split pass: fp32 -> bf16 hi/lo =================
__global__ __launch_bounds__(256)
void split_pass(const float* __restrict__ src, bf16* __restrict__ hi,
                bf16* __restrict__ lo, long n4) {
    for (long i = blockIdx.x * 256 + threadIdx.x; i < n4; i += (long)gridDim.x * 256) {
        float4 v = *(const float4*)(src + i * 4);
        uint32_t h0, l0, h1, l1;
        pack2(v.x, v.y, h0, l0);
        pack2(v.z, v.w, h1, l1);
        *(uint2*)(hi + i * 4) = make_uint2(h0, h1);
        *(uint2*)(lo + i * 4) = make_uint2(l0, l1);
    }
}

// ================= split-bf16 HMMA GEMM: CTA 128x128, Kc=32 =================
#define SM_AH 0
#define SM_AL 10240
#define SM_BH 20480
#define SM_BL 28672
#define BUF_BYTES 36864
#define GEMM_SMEM (2 * BUF_BYTES)

template <bool RELU, bool GATHER, bool MULTI, bool OSPLIT>
__global__ __launch_bounds__(256, 1)
void gemm_mma(const bf16* __restrict__ Ah, const bf16* __restrict__ Al,
              const bf16* __restrict__ Bh0, const bf16* __restrict__ Bl0,
              const bf16* __restrict__ Bh1, const bf16* __restrict__ Bl1,
              const bf16* __restrict__ Bh2, const bf16* __restrict__ Bl2,
              const float* __restrict__ bi0, const float* __restrict__ bi1,
              const float* __restrict__ bi2,
              float* __restrict__ oF0,
              bf16* __restrict__ oH0, bf16* __restrict__ oL0,
              bf16* __restrict__ oH1, bf16* __restrict__ oL1,
              bf16* __restrict__ oH2, bf16* __restrict__ oL2,
              float s0, float s1, float s2,
              const float* __restrict__ resid, const int* __restrict__ gather,
              int K, int N,
              long aStride, long bStride, long biStride, long oStride) {
    extern __shared__ char sm[];
    uint32_t sb = smem_u32(sm);
    int tid = threadIdx.x, wid = tid >> 5, lane = tid & 31;
    int z = blockIdx.z;
    int m0 = blockIdx.y * 128, n0 = blockIdx.x * 128;

    const bf16 *Bh, *Bl; const float* bi; float scale;
    float* oF = nullptr; bf16 *oH = nullptr, *oL = nullptr;
    if (MULTI) {
        Bh = (z == 0) ? Bh0 : (z == 1) ? Bh1 : Bh2;
        Bl = (z == 0) ? Bl0 : (z == 1) ? Bl1 : Bl2;
        bi = (z == 0) ? bi0 : (z == 1) ? bi1 : bi2;
        scale = (z == 0) ? s0 : (z == 1) ? s1 : s2;
        oH = (z == 0) ? oH0 : (z == 1) ? oH1 : oH2;
        oL = (z == 0) ? oL0 : (z == 1) ? oL1 : oL2;
    } else {
        Bh = Bh0 + (long)z * bStride;
        Bl = Bl0 + (long)z * bStride;
        bi = bi0 + (long)z * biStride;
        scale = s0;
        if (OSPLIT) { oH = oH0 + (long)z * oStride; oL = oL0 + (long)z * oStride; }
        else oF = oF0 + (long)z * oStride;
    }
    const bf16* Ahz = Ah + (MULTI ? 0 : (long)z * aStride);
    const bf16* Alz = Al + (MULTI ? 0 : (long)z * aStride);
    const int* gz = GATHER ? (gather + z * CAPV) : nullptr;

    // load mappings (2 vectors per plane for A and B)
    int v0 = tid, v1 = tid + 256;
    int aR0 = v0 >> 2, aC0 = (v0 & 3) * 8;
    int aR1 = v1 >> 2, aC1 = (v1 & 3) * 8;
    long aG0 = (GATHER ? (long)gz[m0 + aR0] : (long)(m0 + aR0)) * K + aC0;
    long aG1 = (GATHER ? (long)gz[m0 + aR1] : (long)(m0 + aR1)) * K + aC1;
    int aS0 = aR0 * 80 + aC0 * 2;
    int aS1 = aR1 * 80 + aC1 * 2;
    int bK0 = v0 >> 4, bN0 = (v0 & 15) * 8;
    int bK1 = v1 >> 4, bN1 = (v1 & 15) * 8;
    long bG0 = (long)bK0 * N + n0 + bN0;
    long bG1 = (long)bK1 * N + n0 + bN1;
    int bS0 = bK0 * 256 + ((bN0 * 2) ^ ((bK0 & 7) << 4));
    int bS1 = bK1 * 256 + ((bN1 * 2) ^ ((bK1 & 7) << 4));

    float c[4][4][4];
#pragma unroll
    for (int mt = 0; mt < 4; mt++)
#pragma unroll
        for (int nt = 0; nt < 4; nt++)
#pragma unroll
            for (int f = 0; f < 4; f++) c[mt][nt][f] = 0.f;

    int wm = wid >> 2, wn = wid & 3;
    int aRowOff = (lane & 7) + ((lane >> 3) & 1) * 8;
    int aColSel = ((lane >> 4) & 1) * 16;
    int bKoff = (lane & 7) + ((lane >> 3) & 1) * 8;
    int bN8 = ((lane >> 4) & 1) * 8;

    uint4 vah0 = *(const uint4*)(Ahz + aG0), vah1 = *(const uint4*)(Ahz + aG1);
    uint4 val0 = *(const uint4*)(Alz + aG0), val1 = *(const uint4*)(Alz + aG1);
    uint4 vbh0 = *(const uint4*)(Bh + bG0),  vbh1 = *(const uint4*)(Bh + bG1);
    uint4 vbl0 = *(const uint4*)(Bl + bG0),  vbl1 = *(const uint4*)(Bl + bG1);

    int nCh = K >> 5;
    for (int ch = 0; ch < nCh; ch++) {
        char* smb = sm + (ch & 1) * BUF_BYTES;
        uint32_t sbuf = sb + (ch & 1) * BUF_BYTES;
        __syncthreads();
        *(uint4*)(smb + SM_AH + aS0) = vah0; *(uint4*)(smb + SM_AH + aS1) = vah1;
        *(uint4*)(smb + SM_AL + aS0) = val0; *(uint4*)(smb + SM_AL + aS1) = val1;
        *(uint4*)(smb + SM_BH + bS0) = vbh0; *(uint4*)(smb + SM_BH + bS1) = vbh1;
        *(uint4*)(smb + SM_BL + bS0) = vbl0; *(uint4*)(smb + SM_BL + bS1) = vbl1;
        __syncthreads();
        if (ch + 1 < nCh) {
            int k0 = (ch + 1) << 5;
            vah0 = *(const uint4*)(Ahz + aG0 + k0); vah1 = *(const uint4*)(Ahz + aG1 + k0);
            val0 = *(const uint4*)(Alz + aG0 + k0); val1 = *(const uint4*)(Alz + aG1 + k0);
            vbh0 = *(const uint4*)(Bh + bG0 + (long)k0 * N);
            vbh1 = *(const uint4*)(Bh + bG1 + (long)k0 * N);
            vbl0 = *(const uint4*)(Bl + bG0 + (long)k0 * N);
            vbl1 = *(const uint4*)(Bl + bG1 + (long)k0 * N);
        }
#pragma unroll
        for (int ks = 0; ks < 2; ks++) {
            uint32_t ah[4][4], al[4][4];
#pragma unroll
            for (int mt = 0; mt < 4; mt++) {
                uint32_t ro = (wm * 64 + mt * 16 + aRowOff) * 80 + ks * 32 + aColSel;
                ldsm_x4(ah[mt], sbuf + SM_AH + ro);
                ldsm_x4(al[mt], sbuf + SM_AL + ro);
            }
            uint32_t bh[2][4], bl[2][4];
#pragma unroll
            for (int nb = 0; nb < 2; nb++) {
                int kk = ks * 16 + bKoff;
                int nn = wn * 32 + nb * 16 + bN8;
                uint32_t off = kk * 256 + ((nn * 2) ^ ((kk & 7) << 4));
                ldsm_x4t(bh[nb], sbuf + SM_BH + off);
                ldsm_x4t(bl[nb], sbuf + SM_BL + off);
            }
#pragma unroll
            for (int mt = 0; mt < 4; mt++)
#pragma unroll
                for (int nt = 0; nt < 4; nt++) {
                    const uint32_t* bp = &bh[nt >> 1][(nt & 1) * 2];
                    const uint32_t* lp = &bl[nt >> 1][(nt & 1) * 2];
                    mma16816(c[mt][nt], ah[mt], bp[0], bp[1]);
                    mma16816(c[mt][nt], ah[mt], lp[0], lp[1]);
                    mma16816(c[mt][nt], al[mt], bp[0], bp[1]);
                }
        }
    }

    int r0 = m0 + wm * 64 + (lane >> 2);
    int col0 = n0 + wn * 32 + (lane & 3) * 2;
#pragma unroll
    for (int mt = 0; mt < 4; mt++) {
#pragma unroll
        for (int nt = 0; nt < 4; nt++) {
            int row = r0 + mt * 16;
            int cn = col0 + nt * 8;
            float2 bb = *(const float2*)(bi + cn);
            float v0x = (c[mt][nt][0] + bb.x) * scale;
            float v0y = (c[mt][nt][1] + bb.y) * scale;
            float v1x = (c[mt][nt][2] + bb.x) * scale;
            float v1y = (c[mt][nt][3] + bb.y) * scale;
            if (resid) {
                float2 ra = *(const float2*)(resid + (long)row * N + cn);
                float2 rb = *(const float2*)(resid + (long)(row + 8) * N + cn);
                v0x += ra.x; v0y += ra.y; v1x += rb.x; v1y += rb.y;
            }
            if (RELU) {
                v0x = fmaxf(v0x, 0.f); v0y = fmaxf(v0y, 0.f);
                v1x = fmaxf(v1x, 0.f); v1y = fmaxf(v1y, 0.f);
            }
            if (OSPLIT) {
                uint32_t h0, l0, h1, l1;
                pack2(v0x, v0y, h0, l0);
                pack2(v1x, v1y, h1, l1);
                *(uint32_t*)(oH + (long)row * N + cn) = h0;
                *(uint32_t*)(oL + (long)row * N + cn) = l0;
                *(uint32_t*)(oH + (long)(row + 8) * N + cn) = h1;
                *(uint32_t*)(oL + (long)(row + 8) * N + cn) = l1;
            } else {
                *(float2*)(oF + (long)row * N + cn) = make_float2(v0x, v0y);
                *(float2*)(oF + (long)(row + 8) * N + cn) = make_float2(v1x, v1y);
            }
        }
    }
}

// ================= scores: S = Q.K^T per (b,h), CTA 128x128, K=64 =================
#define SC_QH 0
#define SC_QL 18432
#define SC_KH 36864
#define SC_KL 55296
#define SC_SMEM 73728

__global__ __launch_bounds__(256, 1)
void scores_mma(const bf16* __restrict__ qh, const bf16* __restrict__ ql,
                const bf16* __restrict__ kh, const bf16* __restrict__ kl,
                float* __restrict__ sc) {
    extern __shared__ char sm[];
    uint32_t sb = smem_u32(sm);
    int tid = threadIdx.x, wid = tid >> 5, lane = tid & 31;
    int bh = blockIdx.z;
    int b = bh >> 4, h = bh & 15;
    int m0 = blockIdx.y * 128, n0 = blockIdx.x * 128;

#pragma unroll
    for (int i = 0; i < 4; i++) {
        int v = tid + 256 * i;
        int row = v >> 3, c8 = (v & 7) * 8;
        int off = row * 144 + c8 * 2;
        long qg = (long)(b * SEQ + m0 + row) * D_MODEL + h * HEAD_D + c8;
        long kg = (long)(b * SEQ + n0 + row) * D_MODEL + h * HEAD_D + c8;
        *(uint4*)(sm + SC_QH + off) = *(const uint4*)(qh + qg);
        *(uint4*)(sm + SC_QL + off) = *(const uint4*)(ql + qg);
        *(uint4*)(sm + SC_KH + off) = *(const uint4*)(kh + kg);
        *(uint4*)(sm + SC_KL + off) = *(const uint4*)(kl + kg);
    }
    __syncthreads();

    float c[4][4][4];
#pragma unroll
    for (int mt = 0; mt < 4; mt++)
#pragma unroll
        for (int nt = 0; nt < 4; nt++)
#pragma unroll
            for (int f = 0; f < 4; f++) c[mt][nt][f] = 0.f;

    int wm = wid >> 2, wn = wid & 3;
    int rowOff = (lane & 7) + ((lane >> 3) & 1) * 8;
    int colSel = ((lane >> 4) & 1) * 16;

#pragma unroll
    for (int ks = 0; ks < 4; ks++) {
        uint32_t ah[4][4], al[4][4];
#pragma unroll
        for (int mt = 0; mt < 4; mt++) {
            uint32_t ro = (wm * 64 + mt * 16 + rowOff) * 144 + ks * 32 + colSel;
            ldsm_x4(ah[mt], sb + SC_QH + ro);
            ldsm_x4(al[mt], sb + SC_QL + ro);
        }
        uint32_t bh_[2][4], bl_[2][4];
#pragma unroll
        for (int nb = 0; nb < 2; nb++) {
            uint32_t ro = (wn * 32 + nb * 16 + rowOff) * 144 + ks * 32 + colSel;
            ldsm_x4(bh_[nb], sb + SC_KH + ro);
            ldsm_x4(bl_[nb], sb + SC_KL + ro);
        }
#pragma unroll
        for (int mt = 0; mt < 4; mt++)
#pragma unroll
            for (int nt = 0; nt < 4; nt++) {
                int nb = nt >> 1, hf = nt & 1;
                uint32_t b0 = bh_[nb][hf], b1 = bh_[nb][hf + 2];
                uint32_t c0 = bl_[nb][hf], c1 = bl_[nb][hf + 2];
                mma16816(c[mt][nt], ah[mt], b0, b1);
                mma16816(c[mt][nt], ah[mt], c0, c1);
                mma16816(c[mt][nt], al[mt], b0, b1);
            }
    }

    long base = (long)bh * SEQ * SEQ;
    int r0 = m0 + wm * 64 + (lane >> 2);
    int col0 = n0 + wn * 32 + (lane & 3) * 2;
#pragma unroll
    for (int mt = 0; mt < 4; mt++)
#pragma unroll
        for (int nt = 0; nt < 4; nt++) {
            int row = r0 + mt * 16, cn = col0 + nt * 8;
            *(float2*)(sc + base + (long)row * SEQ + cn) = make_float2(c[mt][nt][0], c[mt][nt][1]);
            *(float2*)(sc + base + (long)(row + 8) * SEQ + cn) = make_float2(c[mt][nt][2], c[mt][nt][3]);
        }
}

// ================= softmax: fp32 row -> split bf16 P =================
__global__ __launch_bounds__(128)
void softmax_kernel(const float* __restrict__ sc, bf16* __restrict__ ph,
                    bf16* __restrict__ pl) {
    __shared__ float redM[4], redS[4];
    const float* row = sc + (size_t)blockIdx.x * SEQ;
    float v[4]; float m = -1e30f;
#pragma unroll
    for (int i = 0; i < 4; i++) { v[i] = row[threadIdx.x + 128 * i]; m = fmaxf(m, v[i]); }
#pragma unroll
    for (int o = 16; o; o >>= 1) m = fmaxf(m, __shfl_xor_sync(~0u, m, o));
    if ((threadIdx.x & 31) == 0) redM[threadIdx.x >> 5] = m;
    __syncthreads();
    m = fmaxf(fmaxf(redM[0], redM[1]), fmaxf(redM[2], redM[3]));
    float s = 0.f;
#pragma unroll
    for (int i = 0; i < 4; i++) { v[i] = expf(v[i] - m); s += v[i]; }
#pragma unroll
    for (int o = 16; o; o >>= 1) s += __shfl_xor_sync(~0u, s, o);
    if ((threadIdx.x & 31) == 0) redS[threadIdx.x >> 5] = s;
    __syncthreads();
    s = redS[0] + redS[1] + redS[2] + redS[3];
    float inv = 1.f / s;
    size_t base = (size_t)blockIdx.x * SEQ;
#pragma unroll
    for (int i = 0; i < 4; i++) {
        float p = v[i] * inv;
        uint16_t hh, ll;
        split2(p, hh, ll);
        int cidx = threadIdx.x + 128 * i;
        ph[base + cidx] = __ushort_as_bfloat16(hh);
        pl[base + cidx] = __ushort_as_bfloat16(ll);
    }
}

// ================= PV: O = P.V per (b,h), CTA 128x64, Kc=32 =================
#define PV_PH 0
#define PV_PL 10240
#define PV_VH 20480
#define PV_VL 24576
#define PV_BUF 28672
#define PV_SMEM (2 * PV_BUF)

__global__ __launch_bounds__(256, 1)
void pv_mma(const bf16* __restrict__ ph, const bf16* __restrict__ pl,
            const bf16* __restrict__ vh, const bf16* __restrict__ vl,
            bf16* __restrict__ oh, bf16* __restrict__ ol) {
    extern __shared__ char sm[];
    uint32_t sb = smem_u32(sm);
    int tid = threadIdx.x, wid = tid >> 5, lane = tid & 31;
    int bh = blockIdx.y;
    int b = bh >> 4, h = bh & 15;
    int m0 = blockIdx.x * 128;

    int v0 = tid, v1 = tid + 256;
    int aR0 = v0 >> 2, aC0 = (v0 & 3) * 8;
    int aR1 = v1 >> 2, aC1 = (v1 & 3) * 8;
    long pBase = (long)bh * SEQ * SEQ;
    long aG0 = pBase + (long)(m0 + aR0) * SEQ + aC0;
    long aG1 = pBase + (long)(m0 + aR1) * SEQ + aC1;
    int aS0 = aR0 * 80 + aC0 * 2;
    int aS1 = aR1 * 80 + aC1 * 2;
    int bKr = tid >> 3, bN0 = (tid & 7) * 8;
    long bG = (long)(b * SEQ + bKr) * D_MODEL + h * HEAD_D + bN0;
    int bS = bKr * 128 + ((bN0 * 2) ^ ((bKr & 7) << 4));

    float c[4][2][4];
#pragma unroll
    for (int mt = 0; mt < 4; mt++)
#pragma unroll
        for (int nt = 0; nt < 2; nt++)
#pragma unroll
            for (int f = 0; f < 4; f++) c[mt][nt][f] = 0.f;

    int wm = wid >> 2, wn = wid & 3;
    int aRowOff = (lane & 7) + ((lane >> 3) & 1) * 8;
    int aColSel = ((lane >> 4) & 1) * 16;
    int bKoff = (lane & 7) + ((lane >> 3) & 1) * 8;
    int bN8 = ((lane >> 4) & 1) * 8;

    uint4 vph0 = *(const uint4*)(ph + aG0), vph1 = *(const uint4*)(ph + aG1);
    uint4 vpl0 = *(const uint4*)(pl + aG0), vpl1 = *(const uint4*)(pl + aG1);
    uint4 vvh = *(const uint4*)(vh + bG);
    uint4 vvl = *(const uint4*)(vl + bG);

    for (int ch = 0; ch < 16; ch++) {
        char* smb = sm + (ch & 1) * PV_BUF;
        uint32_t sbuf = sb + (ch & 1) * PV_BUF;
        __syncthreads();
        *(uint4*)(smb + PV_PH + aS0) = vph0; *(uint4*)(smb + PV_PH + aS1) = vph1;
        *(uint4*)(smb + PV_PL + aS0) = vpl0; *(uint4*)(smb + PV_PL + aS1) = vpl1;
        *(uint4*)(smb + PV_VH + bS) = vvh;
        *(uint4*)(smb + PV_VL + bS) = vvl;
        __syncthreads();
        if (ch < 15) {
            int k0 = (ch + 1) << 5;
            vph0 = *(const uint4*)(ph + aG0 + k0);
            vph1 = *(const uint4*)(ph + aG1 + k0);
            vpl0 = *(const uint4*)(pl + aG0 + k0);
            vpl1 = *(const uint4*)(pl + aG1 + k0);
            vvh = *(const uint4*)(vh + bG + (long)k0 * D_MODEL);
            vvl = *(const uint4*)(vl + bG + (long)k0 * D_MODEL);
        }
#pragma unroll
        for (int ks = 0; ks < 2; ks++) {
            uint32_t ah[4][4], al[4][4];
#pragma unroll
            for (int mt = 0; mt < 4; mt++) {
                uint32_t ro = (wm * 64 + mt * 16 + aRowOff) * 80 + ks * 32 + aColSel;
                ldsm_x4(ah[mt], sbuf + PV_PH + ro);
                ldsm_x4(al[mt], sbuf + PV_PL + ro);
            }
            uint32_t bh_[4], bl_[4];
            {
                int kk = ks * 16 + bKoff;
                int nn = wn * 16 + bN8;
                uint32_t off = kk * 128 + ((nn * 2) ^ ((kk & 7) << 4));
                ldsm_x4t(bh_, sbuf + PV_VH + off);
                ldsm_x4t(bl_, sbuf + PV_VL + off);
            }
#pragma unroll
            for (int mt = 0; mt < 4; mt++)
#pragma unroll
                for (int nt = 0; nt < 2; nt++) {
                    uint32_t b0 = bh_[nt * 2], b1 = bh_[nt * 2 + 1];
                    uint32_t c0 = bl_[nt * 2], c1 = bl_[nt * 2 + 1];
                    mma16816(c[mt][nt], ah[mt], b0, b1);
                    mma16816(c[mt][nt], ah[mt], c0, c1);
                    mma16816(c[mt][nt], al[mt], b0, b1);
                }
        }
    }

    int r0 = m0 + wm * 64 + (lane >> 2);
    int col0 = wn * 16 + (lane & 3) * 2;
#pragma unroll
    for (int mt = 0; mt < 4; mt++)
#pragma unroll
        for (int nt = 0; nt < 2; nt++) {
            int row = r0 + mt * 16;
            int cn = col0 + nt * 8;
            long o0 = (long)(b * SEQ + row) * D_MODEL + h * HEAD_D + cn;
            long o1 = (long)(b * SEQ + row + 8) * D_MODEL + h * HEAD_D + cn;
            uint32_t h0, l0, h1, l1;
            pack2(c[mt][nt][0], c[mt][nt][1], h0, l0);
            pack2(c[mt][nt][2], c[mt][nt][3], h1, l1);
            *(uint32_t*)(oh + o0) = h0; *(uint32_t*)(ol + o0) = l0;
            *(uint32_t*)(oh + o1) = h1; *(uint32_t*)(ol + o1) = l1;
        }
}

// ================= LayerNorm -> optional fp32 + split bf16 =================
__global__ void ln_kernel(const float* __restrict__ x, const float* __restrict__ gam,
                          const float* __restrict__ bet, float* __restrict__ outF,
                          bf16* __restrict__ oh, bf16* __restrict__ ol) {
    __shared__ float redA[8], redB[8];
    int t = blockIdx.x;
    const float* xr = x + (size_t)t * D_MODEL;
    float v[4]; float s = 0.f;
#pragma unroll
    for (int i = 0; i < 4; i++) { v[i] = xr[threadIdx.x + 256 * i]; s += v[i]; }
#pragma unroll
    for (int o = 16; o; o >>= 1) s += __shfl_xor_sync(~0u, s, o);
    if ((threadIdx.x & 31) == 0) redA[threadIdx.x >> 5] = s;
    __syncthreads();
    if (threadIdx.x == 0) { float r = 0.f; for (int i = 0; i < 8; i++) r += redA[i]; redA[0] = r; }
    __syncthreads();
    float mu = redA[0] * (1.f / D_MODEL);
    float s2 = 0.f;
#pragma unroll
    for (int i = 0; i < 4; i++) { float d = v[i] - mu; s2 += d * d; }
#pragma unroll
    for (int o = 16; o; o >>= 1) s2 += __shfl_xor_sync(~0u, s2, o);
    if ((threadIdx.x & 31) == 0) redB[threadIdx.x >> 5] = s2;
    __syncthreads();
    if (threadIdx.x == 0) { float r = 0.f; for (int i = 0; i < 8; i++) r += redB[i]; redB[0] = r; }
    __syncthreads();
    float rstd = rsqrtf(redB[0] * (1.f / D_MODEL) + 1e-5f);
    size_t base = (size_t)t * D_MODEL;
#pragma unroll
    for (int i = 0; i < 4; i++) {
        int cc = threadIdx.x + 256 * i;
        float r = (v[i] - mu) * rstd * gam[cc] + bet[cc];
        if (outF) outF[base + cc] = r;
        uint16_t hh, ll;
        split2(r, hh, ll);
        oh[base + cc] = __ushort_as_bfloat16(hh);
        ol[base + cc] = __ushort_as_bfloat16(ll);
    }
}

// ================= router / scan / combine =================
__global__ __launch_bounds__(256)
void router_kernel(const float* __restrict__ h2, const float* __restrict__ wr) {
    int t = blockIdx.x * 8 + (threadIdx.x >> 5);
    int lane = threadIdx.x & 31;
    const float* xr = h2 + (long)t * D_MODEL;
    float acc[8];
#pragma unroll
    for (int e = 0; e < 8; e++) acc[e] = 0.f;
    for (int i = lane; i < D_MODEL; i += 32) {
        float xv = xr[i];
        const float* w = wr + i * 8;
#pragma unroll
        for (int e = 0; e < 8; e++) acc[e] = fmaf(xv, w[e], acc[e]);
    }
#pragma unroll
    for (int o = 16; o; o >>= 1)
#pragma unroll
        for (int e = 0; e < 8; e++) acc[e] += __shfl_xor_sync(~0u, acc[e], o);
    if (lane == 0) {
        float m = acc[0]; int t1 = 0;
#pragma unroll
        for (int e = 1; e < 8; e++) if (acc[e] > m) { m = acc[e]; t1 = e; }
        float s = 0.f, pr[8];
#pragma unroll
        for (int e = 0; e < 8; e++) { pr[e] = expf(acc[e] - m); s += pr[e]; }
        float inv = 1.f / s;
        float m2 = -1e30f; int t2 = 0;
#pragma unroll
        for (int e = 0; e < 8; e++) {
            if (e == t1) continue;
            if (acc[e] > m2) { m2 = acc[e]; t2 = e; }
        }
        g_top1[t] = t1; g_top2[t] = t2;
        g_p1[t] = pr[t1] * inv;
        g_p2[t] = pr[t2] * inv;
    }
}

__global__ __launch_bounds__(256)
void scan_kernel() {
    int tid = threadIdx.x;
    for (int i = tid; i < NEXP * CAPV; i += 256) g_disp[i] = 0;
    __syncthreads();
    int e = tid >> 5;
    int lane = tid & 31;
    unsigned lt = (1u << lane) - 1u;
    int base = 0;
    for (int c0 = 0; c0 < N_TOK; c0 += 32) {
        int t = c0 + lane;
        bool f = (g_top1[t] == e);
        unsigned msk = __ballot_sync(~0u, f);
        if (f) {
            int loc = base + __popc(msk & lt);
            if (loc < CAPV) { g_s1[t] = loc; g_disp[e * CAPV + loc] = t; }
            else g_s1[t] = -1;
        }
        base += __popc(msk);
    }
    for (int c0 = 0; c0 < N_TOK; c0 += 32) {
        int t = c0 + lane;
        bool f = (g_top2[t] == e);
        unsigned msk = __ballot_sync(~0u, f);
        if (f) {
            int loc = base + __popc(msk & lt);
            if (loc < CAPV) { g_s2[t] = loc; g_disp[e * CAPV + loc] = t; }
            else g_s2[t] = -1;
        }
        base += __popc(msk);
    }
    __syncthreads();
    for (int t = tid; t < N_TOK; t += 256) {
        float t1 = (g_s1[t] >= 0) ? g_p1[t] : 0.f;
        float t2 = (g_s2[t] >= 0) ? g_p2[t] : 0.f;
        float den = fmaxf(t1 + t2, 1.1920929e-7f);
        g_g1[t] = t1 / den;
        g_g2[t] = t2 / den;
    }
}

__global__ __launch_bounds__(256)
void combine_kernel(float* __restrict__ out) {
    int t = blockIdx.x;
    int s1 = g_s1[t], s2 = g_s2[t];
    float g1 = g_g1[t], g2 = g_g2[t];
    const float* y1 = (s1 >= 0) ? g_y + ((long)g_top1[t] * CAPV + s1) * D_MODEL : 0;
    const float* y2 = (s2 >= 0) ? g_y + ((long)g_top2[t] * CAPV + s2) * D_MODEL : 0;
    long ro = (long)t * D_MODEL;
#pragma unroll
    for (int i = 0; i < 4; i++) {
        int d = threadIdx.x + 256 * i;
        float a = out[ro + d];
        if (y1) a = fmaf(g1, y1[d], a);
        if (y2) a = fmaf(g2, y2[d], a);
        out[ro + d] = a;
    }
}

// ================= launch =================
extern "C" void kernel_launch(void* const* d_in, const int* in_sizes, int n_in,
                              void* d_out, int out_size) {
    const float* x    = (const float*)d_in[0];
    const float* wq   = (const float*)d_in[1];
    const float* bq   = (const float*)d_in[2];
    const float* wk   = (const float*)d_in[3];
    const float* bk   = (const float*)d_in[4];
    const float* wv   = (const float*)d_in[5];
    const float* bv   = (const float*)d_in[6];
    const float* wo   = (const float*)d_in[7];
    const float* bo   = (const float*)d_in[8];
    const float* ln1g = (const float*)d_in[9];
    const float* ln1b = (const float*)d_in[10];
    const float* ln2g = (const float*)d_in[11];
    const float* ln2b = (const float*)d_in[12];
    const float* wr   = (const float*)d_in[13];
    const float* w1   = (const float*)d_in[14];
    const float* b1   = (const float*)d_in[15];
    const float* w2   = (const float*)d_in[16];
    const float* b2   = (const float*)d_in[17];
    float* out = (float*)d_out;

    bf16 *wqh, *wql, *wkh, *wkl, *wvh, *wvl, *woh, *wol, *w1h, *w1l, *w2h, *w2l;
    bf16 *h1h, *h1l, *h2h, *h2l, *qh, *ql, *kh, *kl, *vh, *vl, *ath, *atl;
    bf16 *midh, *midl, *ph, *pl;
    float *h2, *sc, *y;
    int* disp;
    cudaGetSymbolAddress((void**)&wqh, g_wqh); cudaGetSymbolAddress((void**)&wql, g_wql);
    cudaGetSymbolAddress((void**)&wkh, g_wkh); cudaGetSymbolAddress((void**)&wkl, g_wkl);
    cudaGetSymbolAddress((void**)&wvh, g_wvh); cudaGetSymbolAddress((void**)&wvl, g_wvl);
    cudaGetSymbolAddress((void**)&woh, g_woh); cudaGetSymbolAddress((void**)&wol, g_wol);
    cudaGetSymbolAddress((void**)&w1h, g_w1h); cudaGetSymbolAddress((void**)&w1l, g_w1l);
    cudaGetSymbolAddress((void**)&w2h, g_w2h); cudaGetSymbolAddress((void**)&w2l, g_w2l);
    cudaGetSymbolAddress((void**)&h1h, g_h1h); cudaGetSymbolAddress((void**)&h1l, g_h1l);
    cudaGetSymbolAddress((void**)&h2h, g_h2h); cudaGetSymbolAddress((void**)&h2l, g_h2l);
    cudaGetSymbolAddress((void**)&qh, g_qh);   cudaGetSymbolAddress((void**)&ql, g_ql);
    cudaGetSymbolAddress((void**)&kh, g_kh);   cudaGetSymbolAddress((void**)&kl, g_kl);
    cudaGetSymbolAddress((void**)&vh, g_vh);   cudaGetSymbolAddress((void**)&vl, g_vl);
    cudaGetSymbolAddress((void**)&ath, g_ath); cudaGetSymbolAddress((void**)&atl, g_atl);
    cudaGetSymbolAddress((void**)&midh, g_midh); cudaGetSymbolAddress((void**)&midl, g_midl);
    cudaGetSymbolAddress((void**)&ph, g_ph);   cudaGetSymbolAddress((void**)&pl, g_pl);
    cudaGetSymbolAddress((void**)&h2, g_h2);
    cudaGetSymbolAddress((void**)&sc, g_sc);
    cudaGetSymbolAddress((void**)&y, g_y);
    cudaGetSymbolAddress((void**)&disp, g_disp);

    cudaFuncSetAttribute(gemm_mma<false, false, true, true>,
                         cudaFuncAttributeMaxDynamicSharedMemorySize, GEMM_SMEM);
    cudaFuncSetAttribute(gemm_mma<false, false, false, false>,
                         cudaFuncAttributeMaxDynamicSharedMemorySize, GEMM_SMEM);
    cudaFuncSetAttribute(gemm_mma<true, true, false, true>,
                         cudaFuncAttributeMaxDynamicSharedMemorySize, GEMM_SMEM);
    cudaFuncSetAttribute(scores_mma, cudaFuncAttributeMaxDynamicSharedMemorySize, SC_SMEM);
    cudaFuncSetAttribute(pv_mma, cudaFuncAttributeMaxDynamicSharedMemorySize, PV_SMEM);

    // 0) weight splits (fp32 -> bf16 hi/lo, layout preserved [K,N])
    split_pass<<<1024, 256>>>(wq, wqh, wql, 1048576 / 4);
    split_pass<<<1024, 256>>>(wk, wkh, wkl, 1048576 / 4);
    split_pass<<<1024, 256>>>(wv, wvh, wvl, 1048576 / 4);
    split_pass<<<1024, 256>>>(wo, woh, wol, 1048576 / 4);
    split_pass<<<4096, 256>>>(w1, w1h, w1l, 33554432 / 4);
    split_pass<<<4096, 256>>>(w2, w2h, w2l, 33554432 / 4);

    // 1) LN1 -> split
    ln_kernel<<<N_TOK, 256>>>(x, ln1g, ln1b, nullptr, h1h, h1l);

    // 2) QKV fused (split outputs; q pre-scaled)
    gemm_mma<false, false, true, true><<<dim3(8, 16, 3), 256, GEMM_SMEM>>>(
        h1h, h1l, wqh, wql, wkh, wkl, wvh, wvl, bq, bk, bv,
        nullptr, qh, ql, kh, kl, vh, vl, 0.125f, 1.f, 1.f,
        nullptr, nullptr, 1024, 1024, 0, 0, 0, 0);

    // 3) attention
    scores_mma<<<dim3(4, 4, NB * N_HEADS), 256, SC_SMEM>>>(qh, ql, kh, kl, sc);
    softmax_kernel<<<NB * N_HEADS * SEQ, 128>>>(sc, ph, pl);
    pv_mma<<<dim3(4, NB * N_HEADS), 256, PV_SMEM>>>(ph, pl, vh, vl, ath, atl);

    // 4) O projection + residual -> out (fp32)
    gemm_mma<false, false, false, false><<<dim3(8, 16, 1), 256, GEMM_SMEM>>>(
        ath, atl, woh, wol, nullptr, nullptr, nullptr, nullptr, bo, nullptr, nullptr,
        out, nullptr, nullptr, nullptr, nullptr, nullptr, nullptr, 1.f, 0.f, 0.f,
        x, nullptr, 1024, 1024, 0, 0, 0, 0);

    // 5) LN2 -> fp32 (router) + split
    ln_kernel<<<N_TOK, 256>>>(out, ln2g, ln2b, h2, h2h, h2l);

    // 6) router + scan
    router_kernel<<<N_TOK / 8, 256>>>(h2, wr);
    scan_kernel<<<1, 256>>>();

    // 7) FFN1 gathered + relu -> split mid
    gemm_mma<true, true, false, true><<<dim3(32, 4, 8), 256, GEMM_SMEM>>>(
        h2h, h2l, w1h, w1l, nullptr, nullptr, nullptr, nullptr, b1, nullptr, nullptr,
        nullptr, midh, midl, nullptr, nullptr, nullptr, nullptr, 1.f, 0.f, 0.f,
        nullptr, disp, 1024, 4096, 0, (long)D_MODEL * FFN_D, FFN_D, (long)CAPV * FFN_D);

    // 8) FFN2 -> fp32 y (*0.8)
    gemm_mma<false, false, false, false><<<dim3(8, 4, 8), 256, GEMM_SMEM>>>(
        midh, midl, w2h, w2l, nullptr, nullptr, nullptr, nullptr, b2, nullptr, nullptr,
        y, nullptr, nullptr, nullptr, nullptr, nullptr, nullptr, 0.8f, 0.f, 0.f,
        nullptr, nullptr, 4096, 1024,
        (long)CAPV * FFN_D, (long)FFN_D * D_MODEL, D_MODEL, (long)CAPV * D_MODEL);

    // 9) combine
    combine_kernel<<<N_TOK, 256>>>(out);
}